// round 10
// baseline (speedup 1.0000x reference)
#include <cuda_runtime.h>
#include <cuda_bf16.h>

// HeadWise_JSD: out = (0.5/12) * sum p * (log p - log q)   [kl_pm == 0 exactly]
// Streaming reduction over 2 x 201 MB fp32.
// Warp-count scaling confirmed: 32 warps/SM -> 6.2 TB/s, 48 -> 6.74 TB/s.
// R10: 64 warps/SM (8 blocks x 256, the 2048-thread max; 32-reg budget).
// Same light math (2 MUFU + 2 FMUL/elem) and 4-load front batch.

static __device__ __forceinline__ float term(float p, float q) {
    // p * lg2(p/q): MUFU.RCP + FMUL + MUFU.LG2 + FMUL. abs err ~2^-22/op,
    // weighted by sum(p) vs output O(250) -> ~1e-5 worst case. Fine vs 1e-3.
    float r = __fdividef(p, q);
    return p * __log2f(r);
}

static __device__ __forceinline__ float term4(float4 pv, float4 qv) {
    float a = term(pv.x, qv.x) + term(pv.y, qv.y);
    float b = term(pv.z, qv.z) + term(pv.w, qv.w);
    return a + b;
}

__global__ void jsd_zero_kernel(float* out) {
    if (threadIdx.x == 0 && blockIdx.x == 0) out[0] = 0.0f;
}

__global__ __launch_bounds__(256, 8) void jsd_reduce_kernel(
    const float4* __restrict__ p4,
    const float4* __restrict__ q4,
    float* __restrict__ out,
    int n4)
{
    const int stride = gridDim.x * 256;
    int i = blockIdx.x * 256 + threadIdx.x;

    float a0 = 0.0f, a1 = 0.0f;

    // 4 front-batched streaming LDG.128.CS per macro-iter; chip-level MLP
    // comes from 64 warps/SM x 4 lines each.
    for (; i + stride < n4; i += 2 * stride) {
        float4 p0 = __ldcs(p4 + i);
        float4 p1 = __ldcs(p4 + i + stride);
        float4 q0 = __ldcs(q4 + i);
        float4 q1 = __ldcs(q4 + i + stride);
        a0 += term4(p0, q0);
        a1 += term4(p1, q1);
    }
    for (; i < n4; i += stride)
        a0 += term4(__ldcs(p4 + i), __ldcs(q4 + i));

    // log2-units -> nats
    float acc = (a0 + a1) * 0.69314718055994531f;

    #pragma unroll
    for (int o = 16; o; o >>= 1)
        acc += __shfl_xor_sync(0xffffffffu, acc, o);

    __shared__ float smem[8];
    int lane = threadIdx.x & 31;
    int warp = threadIdx.x >> 5;
    if (lane == 0) smem[warp] = acc;
    __syncthreads();

    if (warp == 0) {
        float v = (lane < 8) ? smem[lane] : 0.0f;
        #pragma unroll
        for (int o = 4; o; o >>= 1)
            v += __shfl_xor_sync(0xffffffffu, v, o);
        if (lane == 0)
            atomicAdd(out, v * (0.5f / 12.0f));
    }
}

extern "C" void kernel_launch(void* const* d_in, const int* in_sizes, int n_in,
                              void* d_out, int out_size) {
    const float4* p4 = (const float4*)d_in[0];
    const float4* q4 = (const float4*)d_in[1];
    float* out = (float*)d_out;

    int n  = in_sizes[0];     // 1024*12*4096
    int n4 = n >> 2;          // 12,582,912 float4 pairs

    jsd_zero_kernel<<<1, 32>>>(out);

    // 148 SMs x 8 blocks = 1184 blocks: one full wave at 64 warps/SM
    jsd_reduce_kernel<<<1184, 256>>>(p4, q4, out, n4);
}

// round 11
// speedup vs baseline: 1.0122x; 1.0122x over previous
#include <cuda_runtime.h>
#include <cuda_bf16.h>

// HeadWise_JSD: out = (0.5/12) * sum p * (log p - log q)   [kl_pm == 0 exactly]
// Streaming reduction over 2 x 201 MB fp32.
// Warp-count curve: 32 w/SM -> 6.20, 48 -> 6.74, 64 -> 6.20 TB/s (64w's
// 32-reg budget perturbed codegen). R11 probes 56 warps/SM: 7 blocks x 256
// (reg budget 36 = identical codegen budget to the 6.74 TB/s R9 build).

static __device__ __forceinline__ float term(float p, float q) {
    // p * lg2(p/q): MUFU.RCP + FMUL + MUFU.LG2 + FMUL. abs err ~2^-22/op,
    // weighted by sum(p) vs output O(250) -> ~1e-5 worst case. Fine vs 1e-3.
    float r = __fdividef(p, q);
    return p * __log2f(r);
}

static __device__ __forceinline__ float term4(float4 pv, float4 qv) {
    float a = term(pv.x, qv.x) + term(pv.y, qv.y);
    float b = term(pv.z, qv.z) + term(pv.w, qv.w);
    return a + b;
}

__global__ void jsd_zero_kernel(float* out) {
    if (threadIdx.x == 0 && blockIdx.x == 0) out[0] = 0.0f;
}

__global__ __launch_bounds__(256, 7) void jsd_reduce_kernel(
    const float4* __restrict__ p4,
    const float4* __restrict__ q4,
    float* __restrict__ out,
    int n4)
{
    const int stride = gridDim.x * 256;
    int i = blockIdx.x * 256 + threadIdx.x;

    float a0 = 0.0f, a1 = 0.0f;

    // 4 front-batched streaming LDG.128.CS per macro-iter; chip-level MLP
    // from 56 warps/SM x 4 lines each.
    for (; i + stride < n4; i += 2 * stride) {
        float4 p0 = __ldcs(p4 + i);
        float4 p1 = __ldcs(p4 + i + stride);
        float4 q0 = __ldcs(q4 + i);
        float4 q1 = __ldcs(q4 + i + stride);
        a0 += term4(p0, q0);
        a1 += term4(p1, q1);
    }
    for (; i < n4; i += stride)
        a0 += term4(__ldcs(p4 + i), __ldcs(q4 + i));

    // log2-units -> nats
    float acc = (a0 + a1) * 0.69314718055994531f;

    #pragma unroll
    for (int o = 16; o; o >>= 1)
        acc += __shfl_xor_sync(0xffffffffu, acc, o);

    __shared__ float smem[8];
    int lane = threadIdx.x & 31;
    int warp = threadIdx.x >> 5;
    if (lane == 0) smem[warp] = acc;
    __syncthreads();

    if (warp == 0) {
        float v = (lane < 8) ? smem[lane] : 0.0f;
        #pragma unroll
        for (int o = 4; o; o >>= 1)
            v += __shfl_xor_sync(0xffffffffu, v, o);
        if (lane == 0)
            atomicAdd(out, v * (0.5f / 12.0f));
    }
}

extern "C" void kernel_launch(void* const* d_in, const int* in_sizes, int n_in,
                              void* d_out, int out_size) {
    const float4* p4 = (const float4*)d_in[0];
    const float4* q4 = (const float4*)d_in[1];
    float* out = (float*)d_out;

    int n  = in_sizes[0];     // 1024*12*4096
    int n4 = n >> 2;          // 12,582,912 float4 pairs

    jsd_zero_kernel<<<1, 32>>>(out);

    // 148 SMs x 7 blocks = 1036 blocks: one full wave at 56 warps/SM
    jsd_reduce_kernel<<<1036, 256>>>(p4, q4, out, n4);
}